// round 5
// baseline (speedup 1.0000x reference)
#include <cuda_runtime.h>
#include <cuda_bf16.h>
#include <math.h>
#include <stdint.h>

#define T_TOK 8192
#define D_DIM 1024
#define F_DIM 4096
#define E_EXP 8

// ---------------- scratch (static device globals; no allocations) ----------
__device__ int   g_cnt[E_EXP];
__device__ int   g_off[E_EXP];
__device__ int   g_tok[E_EXP * T_TOK];
__device__ float g_wt [E_EXP * T_TOK];

__device__ __nv_bfloat16 g_xhi [(size_t)T_TOK * D_DIM];
__device__ __nv_bfloat16 g_xlo [(size_t)T_TOK * D_DIM];
__device__ __nv_bfloat16 g_w1hi[(size_t)E_EXP * F_DIM * D_DIM];
__device__ __nv_bfloat16 g_w1lo[(size_t)E_EXP * F_DIM * D_DIM];
__device__ __nv_bfloat16 g_w2hi[(size_t)E_EXP * D_DIM * F_DIM];
__device__ __nv_bfloat16 g_w2lo[(size_t)E_EXP * D_DIM * F_DIM];
__device__ __nv_bfloat16 g_hhi [(size_t)2 * T_TOK * F_DIM];
__device__ __nv_bfloat16 g_hlo [(size_t)2 * T_TOK * F_DIM];

// ---------------- PTX helpers (sm_80+ features only) ------------------------
__device__ __forceinline__ uint32_t smem_u32(const void* p) {
    uint32_t a;
    asm("{ .reg .u64 t; cvta.to.shared.u64 t, %1; cvt.u32.u64 %0, t; }" : "=r"(a) : "l"(p));
    return a;
}
#define CP16(dst, src) asm volatile("cp.async.cg.shared.global [%0], [%1], 16;" :: "r"(dst), "l"(src) : "memory")
#define CP_COMMIT()    asm volatile("cp.async.commit_group;" ::: "memory")
#define CP_WAIT(n)     asm volatile("cp.async.wait_group %0;" :: "n"(n) : "memory")
#define LDX4(r, a)                                                             \
    asm volatile("ldmatrix.sync.aligned.m8n8.x4.shared.b16 {%0,%1,%2,%3}, [%4];" \
        : "=r"((r)[0]), "=r"((r)[1]), "=r"((r)[2]), "=r"((r)[3]) : "r"(a))
#define MMA16(d, a, b0, b1)                                                    \
    asm volatile("mma.sync.aligned.m16n8k16.row.col.f32.bf16.bf16.f32 "        \
        "{%0,%1,%2,%3},{%4,%5,%6,%7},{%8,%9},{%0,%1,%2,%3};"                   \
        : "+f"((d)[0]), "+f"((d)[1]), "+f"((d)[2]), "+f"((d)[3])               \
        : "r"((a)[0]), "r"((a)[1]), "r"((a)[2]), "r"((a)[3]), "r"(b0), "r"(b1))

__device__ __forceinline__ uint32_t pack_bf(__nv_bfloat16 a, __nv_bfloat16 b) {
    return ((uint32_t)__bfloat16_as_ushort(b) << 16) | __bfloat16_as_ushort(a);
}

// SMEM header: [0,512) toks, [512,1536) bias(256 f32), [1536,2048) wts
// Stage buffer (pitch 80B = 32 bf16 + 16B pad):
//   Ahi @0 (128x80=10240), Alo @10240, Bhi @20480 (256x80=20480), Blo @40960
#define SM_STAGE 2048
#define STG_SZ   61440
#define SMEM_DYN (SM_STAGE + 2 * STG_SZ)

// ---------------- init ------------------------------------------------------
__global__ void k_init(float4* __restrict__ out4) {
    int i = blockIdx.x * blockDim.x + threadIdx.x;
    if (i < E_EXP) g_cnt[i] = 0;
    const size_t n4 = (size_t)T_TOK * D_DIM / 4;
    float4 z = make_float4(0.f, 0.f, 0.f, 0.f);
    for (size_t j = i; j < n4; j += (size_t)gridDim.x * blockDim.x) out4[j] = z;
}

// ---------------- split fp32 -> bf16 hi/lo ----------------------------------
__device__ __forceinline__ void split4(__nv_bfloat16* hi, __nv_bfloat16* lo,
                                       const float* s, size_t i) {
    float4 f = ((const float4*)s)[i];
    __nv_bfloat16 h0 = __float2bfloat16(f.x), h1 = __float2bfloat16(f.y);
    __nv_bfloat16 h2 = __float2bfloat16(f.z), h3 = __float2bfloat16(f.w);
    __nv_bfloat16 l0 = __float2bfloat16(f.x - __bfloat162float(h0));
    __nv_bfloat16 l1 = __float2bfloat16(f.y - __bfloat162float(h1));
    __nv_bfloat16 l2 = __float2bfloat16(f.z - __bfloat162float(h2));
    __nv_bfloat16 l3 = __float2bfloat16(f.w - __bfloat162float(h3));
    ((uint2*)hi)[i] = make_uint2(pack_bf(h0, h1), pack_bf(h2, h3));
    ((uint2*)lo)[i] = make_uint2(pack_bf(l0, l1), pack_bf(l2, l3));
}
__global__ void k_split(const float* __restrict__ x, const float* __restrict__ w1,
                        const float* __restrict__ w2) {
    size_t stride = (size_t)gridDim.x * blockDim.x;
    size_t i0 = (size_t)blockIdx.x * blockDim.x + threadIdx.x;
    const size_t nx4 = (size_t)T_TOK * D_DIM / 4;
    const size_t nw4 = (size_t)E_EXP * F_DIM * D_DIM / 4;
    for (size_t i = i0; i < nx4; i += stride) split4(g_xhi, g_xlo, x, i);
    for (size_t i = i0; i < nw4; i += stride) split4(g_w1hi, g_w1lo, w1, i);
    for (size_t i = i0; i < nw4; i += stride) split4(g_w2hi, g_w2lo, w2, i);
}

// ---------------- gating (validated) ----------------------------------------
__global__ void k_gate(const float* __restrict__ x, const float* __restrict__ gw,
                       float* __restrict__ probs_out) {
    int warp = (blockIdx.x * blockDim.x + threadIdx.x) >> 5;
    int lane = threadIdx.x & 31;
    if (warp >= T_TOK) return;
    const float* xr = x + (size_t)warp * D_DIM;
    float acc[E_EXP];
#pragma unroll
    for (int e = 0; e < E_EXP; e++) acc[e] = 0.f;
    for (int k = lane * 4; k < D_DIM; k += 128) {
        float4 xv = *(const float4*)(xr + k);
#pragma unroll
        for (int e = 0; e < E_EXP; e++) {
            float4 wv = *(const float4*)(gw + (size_t)e * D_DIM + k);
            acc[e] += xv.x * wv.x + xv.y * wv.y + xv.z * wv.z + xv.w * wv.w;
        }
    }
#pragma unroll
    for (int e = 0; e < E_EXP; e++)
#pragma unroll
        for (int o = 16; o > 0; o >>= 1) acc[e] += __shfl_xor_sync(0xffffffffu, acc[e], o);
    if (lane == 0) {
        float mx = acc[0];
#pragma unroll
        for (int e = 1; e < E_EXP; e++) mx = fmaxf(mx, acc[e]);
        float p[E_EXP], s = 0.f;
#pragma unroll
        for (int e = 0; e < E_EXP; e++) { p[e] = expf(acc[e] - mx); s += p[e]; }
        float inv = 1.f / s;
#pragma unroll
        for (int e = 0; e < E_EXP; e++) {
            p[e] *= inv;
            probs_out[(size_t)warp * E_EXP + e] = p[e];
        }
        int i0 = 0;
#pragma unroll
        for (int e = 1; e < E_EXP; e++) if (p[e] > p[i0]) i0 = e;
        int i1 = (i0 == 0) ? 1 : 0;
#pragma unroll
        for (int e = 0; e < E_EXP; e++) if (e != i0 && p[e] > p[i1]) i1 = e;
        float denom = p[i0] + p[i1] + 1e-9f;
        int s0 = atomicAdd(&g_cnt[i0], 1);
        g_tok[i0 * T_TOK + s0] = warp; g_wt[i0 * T_TOK + s0] = p[i0] / denom;
        int s1 = atomicAdd(&g_cnt[i1], 1);
        g_tok[i1 * T_TOK + s1] = warp; g_wt[i1 * T_TOK + s1] = p[i1] / denom;
    }
}
__global__ void k_prefix() {
    if (threadIdx.x == 0) {
        int run = 0;
#pragma unroll
        for (int e = 0; e < E_EXP; e++) { g_off[e] = run; run += g_cnt[e]; }
    }
}

// ---------------- GEMM core: block 128x256xk32, warp tile 64x64 -------------
// Per accumulator the term/k order is hh, hl, lh per k16 -- identical FP
// sequence to previous rounds (bit-identical output). Per g: 2 LDSM -> 24 MMA.
#define LDM_SETUP()                                                            \
    const int lane = tid & 31, wid = tid >> 5;                                 \
    const int wm = (wid & 1) * 64, wn = (wid >> 1) * 64;                       \
    uint32_t aav[4];                                                           \
    _Pragma("unroll") for (int mt = 0; mt < 4; ++mt)                           \
        aav[mt] = sb + SM_STAGE +                                              \
            (wm + mt * 16 + (lane & 7) + ((lane >> 3) & 1) * 8) * 80 +         \
            ((lane >> 4) & 1) * 16;                                            \
    uint32_t bbv[4];                                                           \
    _Pragma("unroll") for (int g = 0; g < 4; ++g)                              \
        bbv[g] = sb + SM_STAGE + 20480 +                                       \
            (wn + g * 16 + (lane & 7) + ((lane >> 4) & 1) * 8) * 80 +          \
            ((lane >> 3) & 1) * 16;

#define CHUNK(so)                                                              \
    _Pragma("unroll") for (int kk = 0; kk < 2; ++kk) {                         \
        uint32_t Ah[4][4], Al[4][4];                                           \
        _Pragma("unroll") for (int mt = 0; mt < 4; ++mt) {                     \
            LDX4(Ah[mt], aav[mt] + (so) + kk * 32);                            \
            LDX4(Al[mt], aav[mt] + (so) + 10240 + kk * 32);                    \
        }                                                                      \
        _Pragma("unroll") for (int g = 0; g < 4; ++g) {                        \
            uint32_t Bh[4], Bl[4];                                             \
            LDX4(Bh, bbv[g] + (so) + kk * 32);                                 \
            LDX4(Bl, bbv[g] + (so) + 20480 + kk * 32);                         \
            _Pragma("unroll") for (int mt = 0; mt < 4; ++mt)                   \
                MMA16(acc[mt][2 * g],     Ah[mt], Bh[0], Bh[1]);               \
            _Pragma("unroll") for (int mt = 0; mt < 4; ++mt)                   \
                MMA16(acc[mt][2 * g + 1], Ah[mt], Bh[2], Bh[3]);               \
            _Pragma("unroll") for (int mt = 0; mt < 4; ++mt)                   \
                MMA16(acc[mt][2 * g],     Ah[mt], Bl[0], Bl[1]);               \
            _Pragma("unroll") for (int mt = 0; mt < 4; ++mt)                   \
                MMA16(acc[mt][2 * g + 1], Ah[mt], Bl[2], Bl[3]);               \
            _Pragma("unroll") for (int mt = 0; mt < 4; ++mt)                   \
                MMA16(acc[mt][2 * g],     Al[mt], Bh[0], Bh[1]);               \
            _Pragma("unroll") for (int mt = 0; mt < 4; ++mt)                   \
                MMA16(acc[mt][2 * g + 1], Al[mt], Bh[2], Bh[3]);               \
        }                                                                      \
    }

#define ACC_INIT()                                                             \
    float acc[4][8][4];                                                        \
    _Pragma("unroll") for (int i = 0; i < 4; i++)                              \
        _Pragma("unroll") for (int j = 0; j < 8; j++)                          \
            _Pragma("unroll") for (int k = 0; k < 4; k++) acc[i][j][k] = 0.f;

// ---------------- fc1: h = gelu(X[gather] @ W1e^T + b1) -> bf16 hi/lo -------
__global__ __launch_bounds__(256, 1) void k_fc1_m(const float* __restrict__ b1) {
    const int e = blockIdx.z;
    const int cnt = g_cnt[e];
    const int m0 = blockIdx.y * 128;
    if (m0 >= cnt) return;
    const int n0 = blockIdx.x * 256;

    extern __shared__ __align__(128) char smp[];
    const uint32_t sb = smem_u32(smp);
    int*   toks_s = (int*)smp;
    float* bias_s = (float*)(smp + 512);
    const int tid = threadIdx.x;
    if (tid < 128) toks_s[tid] = g_tok[e * T_TOK + min(m0 + tid, cnt - 1)];
    bias_s[tid] = b1[e * F_DIM + n0 + tid];
    __syncthreads();

    // staging: thread (q = tid&3, r = tid>>2): A rows r, r+64; B rows r+64j
    const int q = tid & 3, r = tid >> 2;
    const uint32_t dA0 = sb + SM_STAGE + r * 80 + q * 16;
    const uint32_t dA1 = dA0 + 64 * 80;
    const uint32_t a0off = (uint32_t)toks_s[r]      * (D_DIM * 2) + q * 16;
    const uint32_t a1off = (uint32_t)toks_s[r + 64] * (D_DIM * 2) + q * 16;
    const char* xhi = (const char*)g_xhi;
    const char* xlo = (const char*)g_xlo;
    const char* wh = (const char*)(g_w1hi + ((size_t)e * F_DIM + n0) * D_DIM) +
                     (size_t)r * (D_DIM * 2) + q * 16;
    const char* wl = (const char*)(g_w1lo + ((size_t)e * F_DIM + n0) * D_DIM) +
                     (size_t)r * (D_DIM * 2) + q * 16;
    const uint32_t dB = sb + SM_STAGE + 20480 + r * 80 + q * 16;

#define STAGE1(c, so) { const uint32_t ko = (uint32_t)(c) * 64;                \
    CP16(dA0 + (so),         xhi + a0off + ko);                                \
    CP16(dA1 + (so),         xhi + a1off + ko);                                \
    CP16(dA0 + (so) + 10240, xlo + a0off + ko);                                \
    CP16(dA1 + (so) + 10240, xlo + a1off + ko);                                \
    _Pragma("unroll") for (int j = 0; j < 4; ++j) {                            \
        CP16(dB + (so) + j * (64 * 80),         wh + (size_t)j * (64 * D_DIM * 2) + ko); \
        CP16(dB + (so) + 20480 + j * (64 * 80), wl + (size_t)j * (64 * D_DIM * 2) + ko); \
    }                                                                          \
    CP_COMMIT(); }

    LDM_SETUP();
    ACC_INIT();

    STAGE1(0, 0);
    const int NC = D_DIM / 32;  // 32
    for (int c = 0; c < NC; ++c) {
        const uint32_t so = (uint32_t)(c & 1) * STG_SZ;
        if (c + 1 < NC) { STAGE1(c + 1, (uint32_t)((c + 1) & 1) * STG_SZ); CP_WAIT(1); }
        else            { CP_WAIT(0); }
        __syncthreads();
        CHUNK(so);
        __syncthreads();
    }

    // epilogue: bias + exact gelu -> split bf16 -> g_hhi/g_hlo
    const int gid2 = lane >> 2, tg = lane & 3;
    const int hbase = g_off[e] + m0;
    uint32_t* ghi = (uint32_t*)g_hhi;
    uint32_t* glo = (uint32_t*)g_hlo;
#pragma unroll
    for (int mt = 0; mt < 4; ++mt)
#pragma unroll
        for (int nt = 0; nt < 8; ++nt) {
            const int n = wn + nt * 8 + tg * 2;
            const float bv0 = bias_s[n], bv1 = bias_s[n + 1];
#pragma unroll
            for (int h = 0; h < 2; ++h) {
                const int m = wm + mt * 16 + gid2 + h * 8;
                if (m0 + m < cnt) {
                    float v0 = acc[mt][nt][2 * h + 0] + bv0;
                    float v1 = acc[mt][nt][2 * h + 1] + bv1;
                    v0 = 0.5f * v0 * (1.f + erff(v0 * 0.7071067811865476f));
                    v1 = 0.5f * v1 * (1.f + erff(v1 * 0.7071067811865476f));
                    __nv_bfloat16 h0 = __float2bfloat16(v0), h1 = __float2bfloat16(v1);
                    __nv_bfloat16 l0 = __float2bfloat16(v0 - __bfloat162float(h0));
                    __nv_bfloat16 l1 = __float2bfloat16(v1 - __bfloat162float(h1));
                    size_t idx = (size_t)(hbase + m) * (F_DIM / 2) + (size_t)(n0 + n) / 2;
                    ghi[idx] = pack_bf(h0, h1);
                    glo[idx] = pack_bf(l0, l1);
                }
            }
        }
}

// ---------------- fc2: out[tok] += w * (h @ W2e^T + b2) ---------------------
__global__ __launch_bounds__(256, 1) void k_fc2_m(const float* __restrict__ b2,
                                                  float* __restrict__ out) {
    const int e = blockIdx.z;
    const int cnt = g_cnt[e];
    const int m0 = blockIdx.y * 128;
    if (m0 >= cnt) return;
    const int n0 = blockIdx.x * 256;

    extern __shared__ __align__(128) char smp[];
    const uint32_t sb = smem_u32(smp);
    int*   toks_s = (int*)smp;
    float* bias_s = (float*)(smp + 512);
    float* wts_s  = (float*)(smp + 1536);
    const int tid = threadIdx.x;
    if (tid < 128) {
        const int slot = min(m0 + tid, cnt - 1);
        toks_s[tid] = g_tok[e * T_TOK + slot];
        wts_s[tid]  = g_wt [e * T_TOK + slot];
    }
    bias_s[tid] = b2[e * D_DIM + n0 + tid];
    __syncthreads();

    const int q = tid & 3, r = tid >> 2;
    const uint32_t dA0 = sb + SM_STAGE + r * 80 + q * 16;
    const uint32_t dA1 = dA0 + 64 * 80;
    const size_t slot0 = (size_t)(g_off[e] + min(m0 + r, cnt - 1));
    const size_t slot1 = (size_t)(g_off[e] + min(m0 + r + 64, cnt - 1));
    const char* ah0 = (const char*)(g_hhi + slot0 * F_DIM) + q * 16;
    const char* ah1 = (const char*)(g_hhi + slot1 * F_DIM) + q * 16;
    const char* al0 = (const char*)(g_hlo + slot0 * F_DIM) + q * 16;
    const char* al1 = (const char*)(g_hlo + slot1 * F_DIM) + q * 16;
    const char* wh = (const char*)(g_w2hi + ((size_t)e * D_DIM + n0) * F_DIM) +
                     (size_t)r * (F_DIM * 2) + q * 16;
    const char* wl = (const char*)(g_w2lo + ((size_t)e * D_DIM + n0) * F_DIM) +
                     (size_t)r * (F_DIM * 2) + q * 16;
    const uint32_t dB = sb + SM_STAGE + 20480 + r * 80 + q * 16;

#define STAGE2(c, so) { const uint32_t ko = (uint32_t)(c) * 64;                \
    CP16(dA0 + (so),         ah0 + ko);                                        \
    CP16(dA1 + (so),         ah1 + ko);                                        \
    CP16(dA0 + (so) + 10240, al0 + ko);                                        \
    CP16(dA1 + (so) + 10240, al1 + ko);                                        \
    _Pragma("unroll") for (int j = 0; j < 4; ++j) {                            \
        CP16(dB + (so) + j * (64 * 80),         wh + (size_t)j * (64 * F_DIM * 2) + ko); \
        CP16(dB + (so) + 20480 + j * (64 * 80), wl + (size_t)j * (64 * F_DIM * 2) + ko); \
    }                                                                          \
    CP_COMMIT(); }

    LDM_SETUP();
    ACC_INIT();

    STAGE2(0, 0);
    const int NC = F_DIM / 32;  // 128
    for (int c = 0; c < NC; ++c) {
        const uint32_t so = (uint32_t)(c & 1) * STG_SZ;
        if (c + 1 < NC) { STAGE2(c + 1, (uint32_t)((c + 1) & 1) * STG_SZ); CP_WAIT(1); }
        else            { CP_WAIT(0); }
        __syncthreads();
        CHUNK(so);
        __syncthreads();
    }

    // epilogue: (acc + bias) * wt -> atomicAdd scatter (2 adds/elem onto 0)
    const int gid2 = lane >> 2, tg = lane & 3;
#pragma unroll
    for (int mt = 0; mt < 4; ++mt)
#pragma unroll
        for (int nt = 0; nt < 8; ++nt) {
            const int n = wn + nt * 8 + tg * 2;
            const float bv0 = bias_s[n], bv1 = bias_s[n + 1];
#pragma unroll
            for (int h = 0; h < 2; ++h) {
                const int m = wm + mt * 16 + gid2 + h * 8;
                if (m0 + m < cnt) {
                    const int   t = toks_s[m];
                    const float w = wts_s[m];
                    float* op = out + (size_t)t * D_DIM + n0 + n;
                    atomicAdd(op,     (acc[mt][nt][2 * h + 0] + bv0) * w);
                    atomicAdd(op + 1, (acc[mt][nt][2 * h + 1] + bv1) * w);
                }
            }
        }
}

// ---------------- launch -----------------------------------------------------
extern "C" void kernel_launch(void* const* d_in, const int* in_sizes, int n_in,
                              void* d_out, int out_size) {
    const float* x  = (const float*)d_in[0];
    const float* gw = (const float*)d_in[1];
    const float* w1 = (const float*)d_in[2];
    const float* b1 = (const float*)d_in[3];
    const float* w2 = (const float*)d_in[4];
    const float* b2 = (const float*)d_in[5];
    float* out   = (float*)d_out;
    float* probs = out + (size_t)T_TOK * D_DIM;

    cudaFuncSetAttribute(k_fc1_m, cudaFuncAttributeMaxDynamicSharedMemorySize, SMEM_DYN);
    cudaFuncSetAttribute(k_fc2_m, cudaFuncAttributeMaxDynamicSharedMemorySize, SMEM_DYN);

    k_init<<<512, 256>>>((float4*)out);
    k_split<<<1024, 256>>>(x, w1, w2);
    k_gate<<<T_TOK / 8, 256>>>(x, gw, probs);
    k_prefix<<<1, 32>>>();
    k_fc1_m<<<dim3(F_DIM / 256, T_TOK / 128, E_EXP), 256, SMEM_DYN>>>(b1);
    k_fc2_m<<<dim3(D_DIM / 256, T_TOK / 128, E_EXP), 256, SMEM_DYN>>>(b2, out);
}